// round 11
// baseline (speedup 1.0000x reference)
#include <cuda_runtime.h>
#include <cstdint>
#include <math.h>

#define TT 2048
#define BB 32
#define DD 512
#define HH 512
#define GG 2048        // 4*H
#define NCTA 128       // persistent CTAs (one wave)
#define RTHREADS 512   // 16 warps
#define NW 16
#define KSL 32         // k-slice per warp
#define GP 35          // gred b-stride pad: conflict-free for both STS and LDS phases

// ---------------- device scratch (static, no allocs) ----------------
__device__ __align__(16) float g_pre[(size_t)TT * GG * BB];   // [t][gate_row][b]
__device__ __align__(16) float g_hbuf[2][BB * HH];            // ping-pong h, [b][k]
__device__ __align__(128) unsigned g_flags[NCTA * 32];        // 1 flag/CTA, own 128B line

// ---------------- packed fp32x2 helpers ----------------
__device__ __forceinline__ unsigned long long pk2(float lo, float hi) {
    unsigned long long r;
    asm("mov.b64 %0, {%1, %2};" : "=l"(r) : "f"(lo), "f"(hi));
    return r;
}
__device__ __forceinline__ void upk2(unsigned long long v, float& lo, float& hi) {
    asm("mov.b64 {%0, %1}, %2;" : "=f"(lo), "=f"(hi) : "l"(v));
}
__device__ __forceinline__ void ffma2(unsigned long long& acc, unsigned long long a,
                                      unsigned long long b) {
    asm("fma.rn.f32x2 %0, %1, %2, %0;" : "+l"(acc) : "l"(a), "l"(b));
}
__device__ __forceinline__ void ldg_cg_2u64(const void* p, unsigned long long& a,
                                            unsigned long long& b) {
    asm volatile("ld.global.cg.v2.u64 {%0, %1}, [%2];" : "=l"(a), "=l"(b) : "l"(p));
}
__device__ __forceinline__ float sigmoid_f(float x) {
    return __fdividef(1.f, 1.f + __expf(-x));
}
__device__ __forceinline__ float tanh_f(float x) {
    return 2.f * __fdividef(1.f, 1.f + __expf(-2.f * x)) - 1.f;
}

// =====================================================================
// Kernel A: pre[t][g][b] = sum_k x[t][b][k] * w_ih[g][k] + b_ih[g]
// (unchanged; ~3.4ms)
// =====================================================================
#define BM 128
#define BN 64
#define BK 16

__global__ __launch_bounds__(256) void pre_gemm(const float* __restrict__ x,
                                                const float* __restrict__ w,
                                                const float* __restrict__ bias) {
    __shared__ __align__(16) float As[BK][BM];
    __shared__ __align__(16) float Bs[BK][BN];

    const int m0 = blockIdx.y * BM;
    const int n0 = blockIdx.x * BN;
    const int tid = threadIdx.x;
    const int tx = tid & 15;
    const int ty = tid >> 4;

    unsigned long long acc[4][4];
#pragma unroll
    for (int i = 0; i < 4; i++)
#pragma unroll
        for (int j = 0; j < 4; j++) acc[i][j] = 0ull;

    for (int k0 = 0; k0 < DD; k0 += BK) {
#pragma unroll
        for (int l = 0; l < 2; l++) {
            int p = tid + l * 256;
            int row = p >> 2, kq = (p & 3) * 4;
            float4 v = *(const float4*)&x[(size_t)(m0 + row) * DD + k0 + kq];
            As[kq + 0][row] = v.x; As[kq + 1][row] = v.y;
            As[kq + 2][row] = v.z; As[kq + 3][row] = v.w;
        }
        {
            int row = tid >> 2, kq = (tid & 3) * 4;
            float4 v = *(const float4*)&w[(size_t)(n0 + row) * DD + k0 + kq];
            Bs[kq + 0][row] = v.x; Bs[kq + 1][row] = v.y;
            Bs[kq + 2][row] = v.z; Bs[kq + 3][row] = v.w;
        }
        __syncthreads();

#pragma unroll
        for (int k = 0; k < BK; k++) {
            float4 a01 = *(const float4*)&As[k][ty * 8];
            float4 a23 = *(const float4*)&As[k][ty * 8 + 4];
            float4 bf  = *(const float4*)&Bs[k][tx * 4];
            unsigned long long A[4] = { pk2(a01.x, a01.y), pk2(a01.z, a01.w),
                                        pk2(a23.x, a23.y), pk2(a23.z, a23.w) };
            unsigned long long Bv[4] = { pk2(bf.x, bf.x), pk2(bf.y, bf.y),
                                         pk2(bf.z, bf.z), pk2(bf.w, bf.w) };
#pragma unroll
            for (int i = 0; i < 4; i++)
#pragma unroll
                for (int j = 0; j < 4; j++) ffma2(acc[i][j], A[i], Bv[j]);
        }
        __syncthreads();
    }

#pragma unroll
    for (int j = 0; j < 4; j++) {
        int n = n0 + tx * 4 + j;
        float bsv = bias[n];
#pragma unroll
        for (int i = 0; i < 4; i++) {
            float lo, hi;
            upk2(acc[i][j], lo, hi);
            int m_lo = m0 + ty * 8 + i * 2;
            int t0 = m_lo >> 5, b_lo = m_lo & 31;
            g_pre[(size_t)t0 * GG * BB + (size_t)n * BB + b_lo] = lo + bsv;
            int m_hi = m_lo + 1;
            int t1 = m_hi >> 5, b_hi = m_hi & 31;
            g_pre[(size_t)t1 * GG * BB + (size_t)n * BB + b_hi] = hi + bsv;
        }
    }
}

// =====================================================================
// Kernel B: persistent recurrent kernel.
//   GEMM lane map: rr = lane&15 (1 gate-row), bh = lane>>4 (16 batches).
//   Warp w owns k in [32w, 32w+32). Weights: 16 f32x2 persistent regs.
//   h read straight from L2 (ld.global.cg.v2.u64); no SMEM staging.
//   Reduce: thread owns gate element (q, cc, bb); per-q nonlinearity,
//   3x shfl.xor gather; q==0 updates register-resident cell state.
//   gred double-buffered by step parity; R8-proven flag-array barrier.
// =====================================================================
struct __align__(16) SmemR {
    float gred[2][NW][16][GP];   // [parity][w][row][b(padded)]  71680 B
};

__global__ __launch_bounds__(RTHREADS, 1) void lstm_recur(
    const float* __restrict__ h0, const float* __restrict__ c0,
    const float* __restrict__ w_hh, const float* __restrict__ b_hh,
    float* __restrict__ out, int write_state) {
    extern __shared__ char smem_raw[];
    SmemR* s = (SmemR*)smem_raw;

    const int tid = threadIdx.x;
    const int w = tid >> 5, lane = tid & 31;
    const int cid = blockIdx.x;
    const int j0 = cid * 4;

    // ---- GEMM mapping: 1 row x 16 batches x 32-k slice per lane ----
    const int rr = lane & 15;          // CTA-local gate row
    const int bh = lane >> 4;          // batch half: batches [16bh, 16bh+16)
    const int Rg = (rr >> 2) * HH + j0 + (rr & 3);   // global gate row

    // ---- persistent weight registers (loaded once for all 2048 steps) ----
    unsigned long long wreg[16];
#pragma unroll
    for (int m = 0; m < 8; m++) {
        float4 v = *(const float4*)&w_hh[(size_t)Rg * HH + w * KSL + 4 * m];
        wreg[2 * m]     = pk2(v.x, v.y);
        wreg[2 * m + 1] = pk2(v.z, v.w);
    }

    // ---- reduce mapping: thread owns gate element (q, cc, bb) ----
    const int cc = w >> 2, bh8 = w & 3;
    const int q = lane >> 3, b8 = lane & 7;
    const int bb = bh8 * 8 + b8;
    const float bhb = b_hh[q * HH + j0 + cc];
    float pq = g_pre[(size_t)(q * HH + j0 + cc) * BB + bb];   // pre[0]
    float cs = 0.f;
    if (q == 0) cs = c0[(size_t)bb * HH + j0 + cc];
    float h_keep = 0.f, c_keep = 0.f;

    for (int t = 0; t < TT; t++) {
        const int par = t & 1;

        // ---- prefetch next step's pre value (hidden under GEMM) ----
        float pqn = 0.f;
        if (t + 1 < TT)
            pqn = __ldcg(&g_pre[(size_t)(t + 1) * GG * BB +
                                (size_t)(q * HH + j0 + cc) * BB + bb]);

        // ---- GEMM from L2: 1 row x 16 batches per lane, k-slice 32 ----
        const float* hb = (t == 0) ? h0 : g_hbuf[t & 1];   // [b][k]
        unsigned long long acc[16];
#pragma unroll 4
        for (int j = 0; j < 16; j++) {
            const char* hp =
                (const char*)(hb + (size_t)(bh * 16 + j) * HH + w * KSL);
            unsigned long long a = 0ull;
#pragma unroll
            for (int m = 0; m < 8; m++) {
                unsigned long long hx, hy;
                ldg_cg_2u64(hp + 16 * m, hx, hy);
                ffma2(a, hx, wreg[2 * m]);
                ffma2(a, hy, wreg[2 * m + 1]);
            }
            acc[j] = a;
        }

        // ---- fold k-parity, publish partials (conflict-free STS) ----
#pragma unroll
        for (int j = 0; j < 16; j++) {
            float lo, hi;
            upk2(acc[j], lo, hi);
            s->gred[par][w][rr][bh * 16 + j] = lo + hi;
        }
        __syncthreads();

        // ---- distributed reduce + gates ----
        float gate = pq + bhb;
#pragma unroll
        for (int ww = 0; ww < NW; ww++)
            gate += s->gred[par][ww][q * 4 + cc][bb];
        float act = (q == 2) ? tanh_f(gate) : sigmoid_f(gate);
        float a1 = __shfl_xor_sync(0xffffffffu, act, 8);    // q^1
        float a2 = __shfl_xor_sync(0xffffffffu, act, 16);   // q^2
        float a3 = __shfl_xor_sync(0xffffffffu, a1, 16);    // q^3
        float hn = 0.f;
        if (q == 0) {
            float iv = act, fv = a1, gv = a2, ov = a3;
            float cn = fv * cs + iv * gv;
            hn = ov * tanh_f(cn);
            cs = cn;
            g_hbuf[(t + 1) & 1][(size_t)bb * HH + j0 + cc] = hn;
            h_keep = hn; c_keep = cn;
        }
        pq = pqn;
        __syncthreads();   // all h stores + gred reads done

        // ---- release own flag; out[t] store off the critical path ----
        if (tid == 0) {
            asm volatile("st.release.gpu.u32 [%0], %1;"
                         :: "l"(&g_flags[cid * 32]), "r"((unsigned)(t + 1))
                         : "memory");
        }
        if (q == 0)
            out[(size_t)t * BB * HH + (size_t)bb * HH + j0 + cc] = hn;

        // ---- flag-array wait: 128 lanes each poll one CTA's flag ----
        if (tid < NCTA) {
            unsigned want = (unsigned)(t + 1);
            unsigned v;
            do {
                asm volatile("ld.acquire.gpu.u32 %0, [%1];"
                             : "=r"(v) : "l"(&g_flags[tid * 32]) : "memory");
            } while (v - want > 1u);   // pass on v == t+1 or t+2
        }
        __syncthreads();
    }

    if (write_state && q == 0) {
        out[(size_t)TT * BB * HH + (size_t)bb * HH + j0 + cc] = h_keep;
        out[(size_t)TT * BB * HH + (size_t)BB * HH + (size_t)bb * HH + j0 + cc] = c_keep;
    }
}

// =====================================================================
// launch
// =====================================================================
extern "C" void kernel_launch(void* const* d_in, const int* in_sizes, int n_in,
                              void* d_out, int out_size) {
    const float* x    = (const float*)d_in[0];
    const float* h0   = (const float*)d_in[1];
    const float* c0   = (const float*)d_in[2];
    const float* w_ih = (const float*)d_in[3];
    const float* w_hh = (const float*)d_in[4];
    const float* b_ih = (const float*)d_in[5];
    const float* b_hh = (const float*)d_in[6];
    float* out = (float*)d_out;

    dim3 gridA(GG / BN, (TT * BB) / BM);
    pre_gemm<<<gridA, 256>>>(x, w_ih, b_ih);

    int smem = (int)sizeof(SmemR);
    cudaFuncSetAttribute(lstm_recur, cudaFuncAttributeMaxDynamicSharedMemorySize, smem);
    int write_state = (out_size >= TT * BB * HH + 2 * BB * HH) ? 1 : 0;
    lstm_recur<<<NCTA, RTHREADS, smem>>>(h0, c0, w_hh, b_hh, out, write_state);
}

// round 12
// speedup vs baseline: 1.4744x; 1.4744x over previous
#include <cuda_runtime.h>
#include <cstdint>
#include <math.h>

#define TT 2048
#define BB 32
#define DD 512
#define HH 512
#define GG 2048        // 4*H
#define NCTA 128       // persistent CTAs (one wave)
#define RTHREADS 512   // 16 warps
#define NW 16
#define KSL 32         // k-slice per warp
#define HSTR 520       // hS row stride (floats): 16B-aligned rows, adjacent rows 32B bank offset
#define GP 35          // gred b-stride pad (conflict-free both phases)

// ---------------- device scratch (static, no allocs) ----------------
__device__ __align__(16) float g_pre[(size_t)TT * GG * BB];   // [t][gate_row][b]
__device__ __align__(16) float g_hbuf[2][BB * HH];            // ping-pong h, [b][k]
__device__ __align__(128) unsigned g_flags[NCTA * 32];        // 1 flag/CTA, own 128B line

// ---------------- packed fp32x2 helpers ----------------
__device__ __forceinline__ unsigned long long pk2(float lo, float hi) {
    unsigned long long r;
    asm("mov.b64 %0, {%1, %2};" : "=l"(r) : "f"(lo), "f"(hi));
    return r;
}
__device__ __forceinline__ void upk2(unsigned long long v, float& lo, float& hi) {
    asm("mov.b64 {%0, %1}, %2;" : "=f"(lo), "=f"(hi) : "l"(v));
}
__device__ __forceinline__ void ffma2(unsigned long long& acc, unsigned long long a,
                                      unsigned long long b) {
    asm("fma.rn.f32x2 %0, %1, %2, %0;" : "+l"(acc) : "l"(a), "l"(b));
}
__device__ __forceinline__ float sigmoid_f(float x) {
    return __fdividef(1.f, 1.f + __expf(-x));
}
__device__ __forceinline__ float tanh_f(float x) {
    return 2.f * __fdividef(1.f, 1.f + __expf(-2.f * x)) - 1.f;
}

// =====================================================================
// Kernel A: pre[t][g][b] = sum_k x[t][b][k] * w_ih[g][k] + b_ih[g]
// (unchanged; ~3.4ms)
// =====================================================================
#define BM 128
#define BN 64
#define BK 16

__global__ __launch_bounds__(256) void pre_gemm(const float* __restrict__ x,
                                                const float* __restrict__ w,
                                                const float* __restrict__ bias) {
    __shared__ __align__(16) float As[BK][BM];
    __shared__ __align__(16) float Bs[BK][BN];

    const int m0 = blockIdx.y * BM;
    const int n0 = blockIdx.x * BN;
    const int tid = threadIdx.x;
    const int tx = tid & 15;
    const int ty = tid >> 4;

    unsigned long long acc[4][4];
#pragma unroll
    for (int i = 0; i < 4; i++)
#pragma unroll
        for (int j = 0; j < 4; j++) acc[i][j] = 0ull;

    for (int k0 = 0; k0 < DD; k0 += BK) {
#pragma unroll
        for (int l = 0; l < 2; l++) {
            int p = tid + l * 256;
            int row = p >> 2, kq = (p & 3) * 4;
            float4 v = *(const float4*)&x[(size_t)(m0 + row) * DD + k0 + kq];
            As[kq + 0][row] = v.x; As[kq + 1][row] = v.y;
            As[kq + 2][row] = v.z; As[kq + 3][row] = v.w;
        }
        {
            int row = tid >> 2, kq = (tid & 3) * 4;
            float4 v = *(const float4*)&w[(size_t)(n0 + row) * DD + k0 + kq];
            Bs[kq + 0][row] = v.x; Bs[kq + 1][row] = v.y;
            Bs[kq + 2][row] = v.z; Bs[kq + 3][row] = v.w;
        }
        __syncthreads();

#pragma unroll
        for (int k = 0; k < BK; k++) {
            float4 a01 = *(const float4*)&As[k][ty * 8];
            float4 a23 = *(const float4*)&As[k][ty * 8 + 4];
            float4 bf  = *(const float4*)&Bs[k][tx * 4];
            unsigned long long A[4] = { pk2(a01.x, a01.y), pk2(a01.z, a01.w),
                                        pk2(a23.x, a23.y), pk2(a23.z, a23.w) };
            unsigned long long Bv[4] = { pk2(bf.x, bf.x), pk2(bf.y, bf.y),
                                         pk2(bf.z, bf.z), pk2(bf.w, bf.w) };
#pragma unroll
            for (int i = 0; i < 4; i++)
#pragma unroll
                for (int j = 0; j < 4; j++) ffma2(acc[i][j], A[i], Bv[j]);
        }
        __syncthreads();
    }

#pragma unroll
    for (int j = 0; j < 4; j++) {
        int n = n0 + tx * 4 + j;
        float bsv = bias[n];
#pragma unroll
        for (int i = 0; i < 4; i++) {
            float lo, hi;
            upk2(acc[i][j], lo, hi);
            int m_lo = m0 + ty * 8 + i * 2;
            int t0 = m_lo >> 5, b_lo = m_lo & 31;
            g_pre[(size_t)t0 * GG * BB + (size_t)n * BB + b_lo] = lo + bsv;
            int m_hi = m_lo + 1;
            int t1 = m_hi >> 5, b_hi = m_hi & 31;
            g_pre[(size_t)t1 * GG * BB + (size_t)n * BB + b_hi] = hi + bsv;
        }
    }
}

// =====================================================================
// Kernel B: persistent recurrent kernel.
//   Weights: 16 f32x2 persistent registers per lane (zero SMEM weight
//   traffic). h staged once per step into bank-engineered SMEM
//   (hS row = 2*(b&15)+(b>>4), stride 520 -> 1 wf per LDS.128).
//   Lane map: rr = lane&15 (gate row), bh = lane>>4 (16 batches).
//   Reduce: thread owns (q, cc, bb); 3x shfl.xor gather; q==0 holds c.
//   R8-proven flag-array grid barrier (window {t+1, t+2}, replay-safe).
// =====================================================================
struct __align__(16) SmemR {
    float hS[BB * HSTR];         // staged h, row-permuted          66560 B
    float gred[NW][16][GP];      // [w][row][b(padded)]             35840 B
};

__global__ __launch_bounds__(RTHREADS, 1) void lstm_recur(
    const float* __restrict__ h0, const float* __restrict__ c0,
    const float* __restrict__ w_hh, const float* __restrict__ b_hh,
    float* __restrict__ out, int write_state) {
    extern __shared__ char smem_raw[];
    SmemR* s = (SmemR*)smem_raw;

    const int tid = threadIdx.x;
    const int w = tid >> 5, lane = tid & 31;
    const int cid = blockIdx.x;
    const int j0 = cid * 4;

    // ---- GEMM mapping: 1 row x 16 batches x 32-k slice per lane ----
    const int rr = lane & 15;                        // CTA-local gate row
    const int bh = lane >> 4;                        // batch half
    const int Rg = (rr >> 2) * HH + j0 + (rr & 3);   // global gate row

    // ---- persistent weight registers (loaded once for all 2048 steps) ----
    unsigned long long wreg[16];
#pragma unroll
    for (int m = 0; m < 8; m++) {
        float4 v = *(const float4*)&w_hh[(size_t)Rg * HH + w * KSL + 4 * m];
        wreg[2 * m]     = pk2(v.x, v.y);
        wreg[2 * m + 1] = pk2(v.z, v.w);
    }

    // ---- reduce mapping: thread owns gate element (q, cc, bb) ----
    const int cc = w >> 2, bh8 = w & 3;
    const int q = lane >> 3, b8 = lane & 7;
    const int bb = bh8 * 8 + b8;
    const float bhb = b_hh[q * HH + j0 + cc];
    float pq = g_pre[(size_t)(q * HH + j0 + cc) * BB + bb];   // pre[0]
    float cs = 0.f;
    if (q == 0) cs = c0[(size_t)bb * HH + j0 + cc];
    float h_keep = 0.f, c_keep = 0.f;

    for (int t = 0; t < TT; t++) {
        // ---- prefetch next step's pre value (hidden under staging/GEMM) ----
        float pqn = 0.f;
        if (t + 1 < TT)
            pqn = __ldcg(&g_pre[(size_t)(t + 1) * GG * BB +
                                (size_t)(q * HH + j0 + cc) * BB + bb]);

        // ---- stage h into SMEM, row-permuted: row(b) = 2*(b&15)+(b>>4) ----
        const float4* hsrc =
            (const float4*)((t == 0) ? h0 : g_hbuf[t & 1]);   // [b][k], 4096 f4
#pragma unroll
        for (int it = 0; it < 8; it++) {
            int i = it * RTHREADS + tid;
            int b = i >> 7, kq = i & 127;
            float4 v = __ldcg(hsrc + i);
            int row = 2 * (b & 15) + (b >> 4);
            *(float4*)&s->hS[row * HSTR + kq * 4] = v;
        }
        __syncthreads();

        // ---- GEMM: 1 row x 16 batches per lane; h from SMEM, w from regs ----
        unsigned long long acc[16];
#pragma unroll
        for (int j = 0; j < 16; j++) {
            const ulonglong2* hp =
                (const ulonglong2*)&s->hS[(2 * j + bh) * HSTR + w * KSL];
            unsigned long long a = 0ull;
#pragma unroll
            for (int m = 0; m < 8; m++) {
                ulonglong2 hv = hp[m];                // {h[k..k+1], h[k+2..k+3]}
                ffma2(a, hv.x, wreg[2 * m]);
                ffma2(a, hv.y, wreg[2 * m + 1]);
            }
            acc[j] = a;
        }

        // ---- fold k-parity, publish partials (conflict-free STS) ----
#pragma unroll
        for (int j = 0; j < 16; j++) {
            float lo, hi;
            upk2(acc[j], lo, hi);
            s->gred[w][rr][bh * 16 + j] = lo + hi;
        }
        __syncthreads();

        // ---- distributed reduce + gates ----
        float gate = pq + bhb;
#pragma unroll
        for (int ww = 0; ww < NW; ww++)
            gate += s->gred[ww][q * 4 + cc][bb];
        float act = (q == 2) ? tanh_f(gate) : sigmoid_f(gate);
        float a1 = __shfl_xor_sync(0xffffffffu, act, 8);    // q^1
        float a2 = __shfl_xor_sync(0xffffffffu, act, 16);   // q^2
        float a3 = __shfl_xor_sync(0xffffffffu, a1, 16);    // q^3
        float hn = 0.f;
        if (q == 0) {
            float iv = act, fv = a1, gv = a2, ov = a3;
            float cn = fv * cs + iv * gv;
            hn = ov * tanh_f(cn);
            cs = cn;
            g_hbuf[(t + 1) & 1][(size_t)bb * HH + j0 + cc] = hn;
            h_keep = hn; c_keep = cn;
        }
        pq = pqn;
        __syncthreads();   // h stores done; gred reads done (single buffer safe)

        // ---- release own flag; out[t] store off the critical path ----
        if (tid == 0) {
            asm volatile("st.release.gpu.u32 [%0], %1;"
                         :: "l"(&g_flags[cid * 32]), "r"((unsigned)(t + 1))
                         : "memory");
        }
        if (q == 0)
            out[(size_t)t * BB * HH + (size_t)bb * HH + j0 + cc] = hn;

        // ---- flag-array wait: 128 lanes each poll one CTA's flag ----
        if (tid < NCTA) {
            unsigned want = (unsigned)(t + 1);
            unsigned v;
            do {
                asm volatile("ld.acquire.gpu.u32 %0, [%1];"
                             : "=r"(v) : "l"(&g_flags[tid * 32]) : "memory");
            } while (v - want > 1u);   // pass on v == t+1 or t+2
        }
        __syncthreads();
    }

    if (write_state && q == 0) {
        out[(size_t)TT * BB * HH + (size_t)bb * HH + j0 + cc] = h_keep;
        out[(size_t)TT * BB * HH + (size_t)BB * HH + (size_t)bb * HH + j0 + cc] = c_keep;
    }
}

// =====================================================================
// launch
// =====================================================================
extern "C" void kernel_launch(void* const* d_in, const int* in_sizes, int n_in,
                              void* d_out, int out_size) {
    const float* x    = (const float*)d_in[0];
    const float* h0   = (const float*)d_in[1];
    const float* c0   = (const float*)d_in[2];
    const float* w_ih = (const float*)d_in[3];
    const float* w_hh = (const float*)d_in[4];
    const float* b_ih = (const float*)d_in[5];
    const float* b_hh = (const float*)d_in[6];
    float* out = (float*)d_out;

    dim3 gridA(GG / BN, (TT * BB) / BM);
    pre_gemm<<<gridA, 256>>>(x, w_ih, b_ih);

    int smem = (int)sizeof(SmemR);
    cudaFuncSetAttribute(lstm_recur, cudaFuncAttributeMaxDynamicSharedMemorySize, smem);
    int write_state = (out_size >= TT * BB * HH + 2 * BB * HH) ? 1 : 0;
    lstm_recur<<<NCTA, RTHREADS, smem>>>(h0, c0, w_hh, b_hh, out, write_state);
}

// round 13
// speedup vs baseline: 1.6561x; 1.1232x over previous
#include <cuda_runtime.h>
#include <cstdint>
#include <math.h>

#define TT 2048
#define BB 32
#define DD 512
#define HH 512
#define GG 2048        // 4*H
#define NCTA 128       // persistent CTAs (one wave)
#define RTHREADS 512   // 16 warps
#define NW 16
#define KSL 32         // k-slice per warp
#define HSTR 520       // hS row stride (floats): rows 16B-aligned, adjacent rows +32B mod 128
#define GP 35          // gred b-stride pad

// ---------------- device scratch (static, no allocs) ----------------
__device__ __align__(16) float g_pre[(size_t)TT * GG * BB];   // [t][gate_row][b]
__device__ __align__(16) float g_hbuf[2][BB * HH];            // ping-pong h, [b][k]
__device__ __align__(128) unsigned g_flags[NCTA * 32];        // 1 flag/CTA, own 128B line

// ---------------- packed fp32x2 helpers ----------------
__device__ __forceinline__ unsigned long long pk2(float lo, float hi) {
    unsigned long long r;
    asm("mov.b64 %0, {%1, %2};" : "=l"(r) : "f"(lo), "f"(hi));
    return r;
}
__device__ __forceinline__ void upk2(unsigned long long v, float& lo, float& hi) {
    asm("mov.b64 {%0, %1}, %2;" : "=f"(lo), "=f"(hi) : "l"(v));
}
__device__ __forceinline__ void ffma2(unsigned long long& acc, unsigned long long a,
                                      unsigned long long b) {
    asm("fma.rn.f32x2 %0, %1, %2, %0;" : "+l"(acc) : "l"(a), "l"(b));
}
__device__ __forceinline__ float sigmoid_f(float x) {
    return __fdividef(1.f, 1.f + __expf(-x));
}
__device__ __forceinline__ float tanh_f(float x) {
    return 2.f * __fdividef(1.f, 1.f + __expf(-2.f * x)) - 1.f;
}

// =====================================================================
// Kernel A: pre[t][g][b] = sum_k x[t][b][k] * w_ih[g][k] + b_ih[g]
// (unchanged; ~3.4ms)
// =====================================================================
#define BM 128
#define BN 64
#define BK 16

__global__ __launch_bounds__(256) void pre_gemm(const float* __restrict__ x,
                                                const float* __restrict__ w,
                                                const float* __restrict__ bias) {
    __shared__ __align__(16) float As[BK][BM];
    __shared__ __align__(16) float Bs[BK][BN];

    const int m0 = blockIdx.y * BM;
    const int n0 = blockIdx.x * BN;
    const int tid = threadIdx.x;
    const int tx = tid & 15;
    const int ty = tid >> 4;

    unsigned long long acc[4][4];
#pragma unroll
    for (int i = 0; i < 4; i++)
#pragma unroll
        for (int j = 0; j < 4; j++) acc[i][j] = 0ull;

    for (int k0 = 0; k0 < DD; k0 += BK) {
#pragma unroll
        for (int l = 0; l < 2; l++) {
            int p = tid + l * 256;
            int row = p >> 2, kq = (p & 3) * 4;
            float4 v = *(const float4*)&x[(size_t)(m0 + row) * DD + k0 + kq];
            As[kq + 0][row] = v.x; As[kq + 1][row] = v.y;
            As[kq + 2][row] = v.z; As[kq + 3][row] = v.w;
        }
        {
            int row = tid >> 2, kq = (tid & 3) * 4;
            float4 v = *(const float4*)&w[(size_t)(n0 + row) * DD + k0 + kq];
            Bs[kq + 0][row] = v.x; Bs[kq + 1][row] = v.y;
            Bs[kq + 2][row] = v.z; Bs[kq + 3][row] = v.w;
        }
        __syncthreads();

#pragma unroll
        for (int k = 0; k < BK; k++) {
            float4 a01 = *(const float4*)&As[k][ty * 8];
            float4 a23 = *(const float4*)&As[k][ty * 8 + 4];
            float4 bf  = *(const float4*)&Bs[k][tx * 4];
            unsigned long long A[4] = { pk2(a01.x, a01.y), pk2(a01.z, a01.w),
                                        pk2(a23.x, a23.y), pk2(a23.z, a23.w) };
            unsigned long long Bv[4] = { pk2(bf.x, bf.x), pk2(bf.y, bf.y),
                                         pk2(bf.z, bf.z), pk2(bf.w, bf.w) };
#pragma unroll
            for (int i = 0; i < 4; i++)
#pragma unroll
                for (int j = 0; j < 4; j++) ffma2(acc[i][j], A[i], Bv[j]);
        }
        __syncthreads();
    }

#pragma unroll
    for (int j = 0; j < 4; j++) {
        int n = n0 + tx * 4 + j;
        float bsv = bias[n];
#pragma unroll
        for (int i = 0; i < 4; i++) {
            float lo, hi;
            upk2(acc[i][j], lo, hi);
            int m_lo = m0 + ty * 8 + i * 2;
            int t0 = m_lo >> 5, b_lo = m_lo & 31;
            g_pre[(size_t)t0 * GG * BB + (size_t)n * BB + b_lo] = lo + bsv;
            int m_hi = m_lo + 1;
            int t1 = m_hi >> 5, b_hi = m_hi & 31;
            g_pre[(size_t)t1 * GG * BB + (size_t)n * BB + b_hi] = hi + bsv;
        }
    }
}

// =====================================================================
// Kernel B: persistent recurrent kernel.
//   Lane map: rh = lane>>2 (rows 2rh, 2rh+1), bq = lane&3 (batches 4j+bq).
//   Weights: 32 persistent f32x2 regs/lane. h staged per-warp into
//   hS[b][k] (stride 520): GEMM LDS.128 carries 4 distinct 16B chunks
//   (offsets 0/32/64/96 mod 128) -> 1 wf, 64B useful.
//   Sync: per-warp producer flag waits (8 flags, window {t,t+1}) +
//   two CTA-wide syncthreads. Flags released once per step by tid 0.
// =====================================================================
struct __align__(16) SmemR {
    float hS[BB * HSTR];         // staged h, [b][k]               66560 B
    float gred[NW][16][GP];      // [w][row][b(padded)]            35840 B
};

__global__ __launch_bounds__(RTHREADS, 1) void lstm_recur(
    const float* __restrict__ h0, const float* __restrict__ c0,
    const float* __restrict__ w_hh, const float* __restrict__ b_hh,
    float* __restrict__ out, int write_state) {
    extern __shared__ char smem_raw[];
    SmemR* s = (SmemR*)smem_raw;

    const int tid = threadIdx.x;
    const int w = tid >> 5, lane = tid & 31;
    const int cid = blockIdx.x;
    const int j0 = cid * 4;

    // ---- GEMM mapping: 2 rows x 8 batches x 32-k slice per lane ----
    const int rh = lane >> 2, bq = lane & 3;
    const int r0 = 2 * rh, r1 = r0 + 1;                      // CTA-local rows
    const int R0 = (r0 >> 2) * HH + j0 + (r0 & 3);           // global rows
    const int R1 = (r1 >> 2) * HH + j0 + (r1 & 3);

    // ---- persistent weight registers (loaded once for all 2048 steps) ----
    unsigned long long wA[16], wB[16];
#pragma unroll
    for (int m = 0; m < 8; m++) {
        float4 a = *(const float4*)&w_hh[(size_t)R0 * HH + w * KSL + 4 * m];
        wA[2 * m] = pk2(a.x, a.y); wA[2 * m + 1] = pk2(a.z, a.w);
        float4 b = *(const float4*)&w_hh[(size_t)R1 * HH + w * KSL + 4 * m];
        wB[2 * m] = pk2(b.x, b.y); wB[2 * m + 1] = pk2(b.z, b.w);
    }

    // ---- staging mapping: lane = (c k-chunk, rg row-group) ----
    const int sc = lane & 7, srg = lane >> 3;

    // ---- reduce mapping: thread owns gate element (q, cc, bb) ----
    const int cc = w >> 2, bh8 = w & 3;
    const int q = lane >> 3, b8 = lane & 7;
    const int bb = bh8 * 8 + b8;
    const float bhb = b_hh[q * HH + j0 + cc];
    float pq = g_pre[(size_t)(q * HH + j0 + cc) * BB + bb];   // pre[0]
    float cs = 0.f;
    if (q == 0) cs = c0[(size_t)bb * HH + j0 + cc];
    float h_keep = 0.f, c_keep = 0.f;

    for (int t = 0; t < TT; t++) {
        // ---- prefetch next step's pre value (independent of flags) ----
        float pqn = 0.f;
        if (t + 1 < TT)
            pqn = __ldcg(&g_pre[(size_t)(t + 1) * GG * BB +
                                (size_t)(q * HH + j0 + cc) * BB + bb]);

        // ---- per-warp producer wait: warp w needs cells [32w, 32w+32)
        //      = producer CTAs [8w, 8w+8). Window {t, t+1}, skip at t=0. ----
        if (t > 0) {
            if (lane < 8) {
                const unsigned* fp = &g_flags[(w * 8 + lane) * 32];
                unsigned want = (unsigned)t, v;
                do {
                    asm volatile("ld.acquire.gpu.u32 %0, [%1];"
                                 : "=r"(v) : "l"(fp) : "memory");
                } while (v - want > 1u);   // pass on v == t or t+1
            }
            __syncwarp();
        }

        // ---- per-warp stage: own 32-k slice for all 32 batches ----
        const float* hsrc = (t == 0) ? h0 : g_hbuf[t & 1];   // [b][k]
#pragma unroll
        for (int i = 0; i < 8; i++) {
            int b = srg + 4 * i;
            float4 v = __ldcg((const float4*)(hsrc + (size_t)b * HH + w * KSL) + sc);
            *(float4*)&s->hS[b * HSTR + w * KSL + 4 * sc] = v;
        }
        __syncwarp();

        // ---- GEMM: 2 rows x 8 batches per lane; h from SMEM, w from regs ----
        unsigned long long accA[8], accB[8];
#pragma unroll
        for (int j = 0; j < 8; j++) { accA[j] = 0ull; accB[j] = 0ull; }
#pragma unroll
        for (int j = 0; j < 8; j++) {
            const ulonglong2* hp =
                (const ulonglong2*)&s->hS[(4 * j + bq) * HSTR + w * KSL];
            unsigned long long a0 = 0ull, a1 = 0ull;
#pragma unroll
            for (int m = 0; m < 8; m++) {
                ulonglong2 hv = hp[m];               // k-pairs 2m, 2m+1
                ffma2(a0, hv.x, wA[2 * m]);
                ffma2(a1, hv.x, wB[2 * m]);
                ffma2(a0, hv.y, wA[2 * m + 1]);
                ffma2(a1, hv.y, wB[2 * m + 1]);
            }
            accA[j] = a0; accB[j] = a1;
        }

        // ---- fold k-parity, publish partials ----
#pragma unroll
        for (int j = 0; j < 8; j++) {
            float lo, hi;
            upk2(accA[j], lo, hi);
            s->gred[w][r0][4 * j + bq] = lo + hi;
            upk2(accB[j], lo, hi);
            s->gred[w][r1][4 * j + bq] = lo + hi;
        }
        __syncthreads();

        // ---- distributed reduce + gates ----
        float gate = pq + bhb;
#pragma unroll
        for (int ww = 0; ww < NW; ww++)
            gate += s->gred[ww][q * 4 + cc][bb];
        float act = (q == 2) ? tanh_f(gate) : sigmoid_f(gate);
        float a1 = __shfl_xor_sync(0xffffffffu, act, 8);    // q^1
        float a2 = __shfl_xor_sync(0xffffffffu, act, 16);   // q^2
        float a3 = __shfl_xor_sync(0xffffffffu, a1, 16);    // q^3
        float hn = 0.f;
        if (q == 0) {
            float iv = act, fv = a1, gv = a2, ov = a3;
            float cn = fv * cs + iv * gv;
            hn = ov * tanh_f(cn);
            cs = cn;
            g_hbuf[(t + 1) & 1][(size_t)bb * HH + j0 + cc] = hn;
            h_keep = hn; c_keep = cn;
        }
        pq = pqn;
        __syncthreads();   // all h writes + gred reads complete

        // ---- release own flag; out[t] store off the critical path ----
        if (tid == 0) {
            asm volatile("st.release.gpu.u32 [%0], %1;"
                         :: "l"(&g_flags[cid * 32]), "r"((unsigned)(t + 1))
                         : "memory");
        }
        if (q == 0)
            out[(size_t)t * BB * HH + (size_t)bb * HH + j0 + cc] = hn;
    }

    if (write_state && q == 0) {
        out[(size_t)TT * BB * HH + (size_t)bb * HH + j0 + cc] = h_keep;
        out[(size_t)TT * BB * HH + (size_t)BB * HH + (size_t)bb * HH + j0 + cc] = c_keep;
    }
}

// =====================================================================
// launch
// =====================================================================
extern "C" void kernel_launch(void* const* d_in, const int* in_sizes, int n_in,
                              void* d_out, int out_size) {
    const float* x    = (const float*)d_in[0];
    const float* h0   = (const float*)d_in[1];
    const float* c0   = (const float*)d_in[2];
    const float* w_ih = (const float*)d_in[3];
    const float* w_hh = (const float*)d_in[4];
    const float* b_ih = (const float*)d_in[5];
    const float* b_hh = (const float*)d_in[6];
    float* out = (float*)d_out;

    dim3 gridA(GG / BN, (TT * BB) / BM);
    pre_gemm<<<gridA, 256>>>(x, w_ih, b_ih);

    int smem = (int)sizeof(SmemR);
    cudaFuncSetAttribute(lstm_recur, cudaFuncAttributeMaxDynamicSharedMemorySize, smem);
    int write_state = (out_size >= TT * BB * HH + 2 * BB * HH) ? 1 : 0;
    lstm_recur<<<NCTA, RTHREADS, smem>>>(h0, c0, w_hh, b_hh, out, write_state);
}